// round 10
// baseline (speedup 1.0000x reference)
#include <cuda_runtime.h>
#include <cuda_bf16.h>
#include <cstdint>

// ---------------------------------------------------------------------------
// BoxMultiHeadedAttention  (B=16, N=256, D=512, H=8, d_k=64, dim_g=64)
//
//  K1 fused_qkv_geo : blocks 0..1535  -> q,k,v GEMM (tf32 mma, fragment-order
//                     smem staging, 12xLDS.128 per 32k-chunk per thread)
//                     blocks 1536..   -> geo bias (concurrent)
//  K2 attn_core     : O = softmax(bias + qk^T/8) @ V  (fused, tf32 mma)
//  K3 outproj       : out = attn @ Wo + bo
// ---------------------------------------------------------------------------

#define Bz   16
#define Nn   256
#define Dm   512
#define Hh   8
#define DK   64

__device__ float g_q   [Bz*Hh*Nn*DK];
__device__ float g_k   [Bz*Hh*Nn*DK];
__device__ float g_v   [Bz*Hh*Nn*DK];
__device__ float g_bias[Bz*Hh*Nn*Nn];     // geo bias (read-only after K1)
__device__ float g_attn[Bz*Nn*Dm];

__device__ __forceinline__ float to_tf32(float x) {
    uint32_t u;
    asm("cvt.rna.tf32.f32 %0, %1;" : "=r"(u) : "f"(x));
    return __uint_as_float(u);
}

__device__ __forceinline__ void mma_tf32(float c[4],
                                         uint32_t a0, uint32_t a1, uint32_t a2, uint32_t a3,
                                         uint32_t b0, uint32_t b1) {
    asm volatile(
        "mma.sync.aligned.m16n8k8.row.col.f32.tf32.tf32.f32 "
        "{%0,%1,%2,%3}, {%4,%5,%6,%7}, {%8,%9}, {%0,%1,%2,%3};\n"
        : "+f"(c[0]), "+f"(c[1]), "+f"(c[2]), "+f"(c[3])
        : "r"(a0), "r"(a1), "r"(a2), "r"(a3), "r"(b0), "r"(b1));
}

__device__ __forceinline__ float4 tf32_4(float4 v) {
    v.x = to_tf32(v.x); v.y = to_tf32(v.y);
    v.z = to_tf32(v.z); v.w = to_tf32(v.w);
    return v;
}

// ---------------------------------------------------------------------------
// tf32 GEMM body, fragment-order staging.
// C[64x64 tile] = A[.,512] @ W[512,512] + bias.  256 threads / 8 warps,
// warp tile 32x16, k-chunk 32, double-buffered.
//
// A smem layout: off = row*36 + tig*8 + j            (j = 2*ks8 + khalf)
// B smem layout: off = nc*36 + (nc>>3)*4 + tig*8 + j
// Readers fetch per chunk: A 8x LDS.128, B 4x LDS.128 (all frag regs).
// ---------------------------------------------------------------------------
template <bool PERM>
__device__ __forceinline__ void gemm_tf32_body(const float* __restrict__ A,
                                               const float* __restrict__ W,
                                               const float* __restrict__ bias,
                                               float* __restrict__ C,
                                               int rowBase, int colBase)
{
    __shared__ float As[2][2304];     // 64*36
    __shared__ float Bs[2][2336];     // 63*36 + 7*4 + 31 + 1

    const int t    = threadIdx.x;
    const int lane = t & 31;
    const int w    = t >> 5;
    const int g    = lane >> 2;
    const int tig  = lane & 3;
    const int wm   = w >> 2;          // 0..1
    const int wn   = w & 3;           // 0..3

    // staging coordinates
    const int ar = t >> 2,  ak = (t & 3) * 8;   // A: 64 rows x 32 k, 8/thread
    const int bk = t >> 3,  bn = (t & 7) * 8;   // B: 32 k x 64 n, 8/thread
    const float* Ap = A + (size_t)(rowBase + ar) * Dm + ak;
    const float* Wp = W + (size_t)bk * Dm + colBase + bn;

    // A store slots: k = ak+i -> off = ar*36 + (i&3)*8 + (t&3)*2 + (i>>2)
    const int aBase = ar * 36 + (t & 3) * 2;
    // B store slots: col nc=bn+i, k=bk ->
    //   off = nc*36 + (t&7)*4 + (bk&3)*8 + ((bk>>3)*2 + ((bk>>2)&1))
    const int bBase = bn * 36 + (t & 7) * 4 + (bk & 3) * 8
                    + ((bk >> 3) * 2 + ((bk >> 2) & 1));

    float acc[2][2][4];
#pragma unroll
    for (int mt = 0; mt < 2; ++mt)
#pragma unroll
        for (int nt = 0; nt < 2; ++nt)
#pragma unroll
            for (int i = 0; i < 4; ++i) acc[mt][nt][i] = 0.0f;

    // ---- stage chunk 0 into buf 0 ----
    {
        float4 a0 = tf32_4(*(const float4*)(Ap));
        float4 a1 = tf32_4(*(const float4*)(Ap + 4));
        float av[8] = {a0.x, a0.y, a0.z, a0.w, a1.x, a1.y, a1.z, a1.w};
#pragma unroll
        for (int i = 0; i < 8; ++i)
            As[0][aBase + (i & 3) * 8 + (i >> 2)] = av[i];
        float4 b0 = tf32_4(*(const float4*)(Wp));
        float4 b1 = tf32_4(*(const float4*)(Wp + 4));
        float bv[8] = {b0.x, b0.y, b0.z, b0.w, b1.x, b1.y, b1.z, b1.w};
#pragma unroll
        for (int i = 0; i < 8; ++i)
            Bs[0][bBase + i * 36] = bv[i];
    }
    __syncthreads();

    // reader bases
    const int mr0 = wm * 32 + g;              // rows mr0, mr0+8, mr0+16, mr0+24
    const int nc0 = wn * 16 + g;              // cols nc0, nc0+8
    const int aRd0 = mr0 * 36 + tig * 8;
    const int bRd0 = nc0 * 36 + (nc0 >> 3) * 4 + tig * 8;
    const int bRd1 = (nc0 + 8) * 36 + ((nc0 + 8) >> 3) * 4 + tig * 8;

    const int NK = Dm / 32;          // 16
    for (int it = 0; it < NK; ++it) {
        float4 pa0, pa1, pb0, pb1;
        const bool more = (it + 1 < NK);
        if (more) {
            const int k0 = (it + 1) * 32;
            pa0 = *(const float4*)(Ap + k0);
            pa1 = *(const float4*)(Ap + k0 + 4);
            pb0 = *(const float4*)(Wp + (size_t)k0 * Dm);
            pb1 = *(const float4*)(Wp + (size_t)k0 * Dm + 4);
        }

        const int buf = it & 1;

        // ---- load ALL fragments for this chunk: 8 + 4 LDS.128 ----
        float Afr[2][2][8];          // [mt][row / row+8][j]
#pragma unroll
        for (int mt = 0; mt < 2; ++mt) {
            int base0 = aRd0 + mt * 16 * 36;
            int base1 = base0 + 8 * 36;
            *(float4*)&Afr[mt][0][0] = *(const float4*)&As[buf][base0];
            *(float4*)&Afr[mt][0][4] = *(const float4*)&As[buf][base0 + 4];
            *(float4*)&Afr[mt][1][0] = *(const float4*)&As[buf][base1];
            *(float4*)&Afr[mt][1][4] = *(const float4*)&As[buf][base1 + 4];
        }
        float Bfr[2][8];             // [nt][j]
        *(float4*)&Bfr[0][0] = *(const float4*)&Bs[buf][bRd0];
        *(float4*)&Bfr[0][4] = *(const float4*)&Bs[buf][bRd0 + 4];
        *(float4*)&Bfr[1][0] = *(const float4*)&Bs[buf][bRd1];
        *(float4*)&Bfr[1][4] = *(const float4*)&Bs[buf][bRd1 + 4];

        // ---- 16 mma ----
#pragma unroll
        for (int m = 0; m < 4; ++m)
#pragma unroll
            for (int mt = 0; mt < 2; ++mt)
#pragma unroll
                for (int nt = 0; nt < 2; ++nt)
                    mma_tf32(acc[mt][nt],
                             __float_as_uint(Afr[mt][0][2 * m]),
                             __float_as_uint(Afr[mt][1][2 * m]),
                             __float_as_uint(Afr[mt][0][2 * m + 1]),
                             __float_as_uint(Afr[mt][1][2 * m + 1]),
                             __float_as_uint(Bfr[nt][2 * m]),
                             __float_as_uint(Bfr[nt][2 * m + 1]));

        if (more) {
            const int nb = 1 - buf;
            pa0 = tf32_4(pa0); pa1 = tf32_4(pa1);
            float av[8] = {pa0.x, pa0.y, pa0.z, pa0.w, pa1.x, pa1.y, pa1.z, pa1.w};
#pragma unroll
            for (int i = 0; i < 8; ++i)
                As[nb][aBase + (i & 3) * 8 + (i >> 2)] = av[i];
            pb0 = tf32_4(pb0); pb1 = tf32_4(pb1);
            float bv[8] = {pb0.x, pb0.y, pb0.z, pb0.w, pb1.x, pb1.y, pb1.z, pb1.w};
#pragma unroll
            for (int i = 0; i < 8; ++i)
                Bs[nb][bBase + i * 36] = bv[i];
        }
        __syncthreads();
    }

#pragma unroll
    for (int mt = 0; mt < 2; ++mt) {
#pragma unroll
        for (int nt = 0; nt < 2; ++nt) {
            int r0 = rowBase + wm * 32 + mt * 16 + g;
            int c0 = colBase + wn * 16 + nt * 8 + 2 * tig;
            float v00 = acc[mt][nt][0] + bias[c0];
            float v01 = acc[mt][nt][1] + bias[c0 + 1];
            float v10 = acc[mt][nt][2] + bias[c0];
            float v11 = acc[mt][nt][3] + bias[c0 + 1];
            if (PERM) {
                int b_ = r0 >> 8, n_ = r0 & 255, h_ = c0 >> 6, d_ = c0 & 63;
                float* p0 = C + ((((b_ * Hh + h_) * Nn) + n_) * DK + d_);
                p0[0] = v00; p0[1] = v01;
                int r1 = r0 + 8;
                int b1_ = r1 >> 8, n1_ = r1 & 255;
                float* p1 = C + ((((b1_ * Hh + h_) * Nn) + n1_) * DK + d_);
                p1[0] = v10; p1[1] = v11;
            } else {
                *(float2*)(C + (size_t)r0 * Dm + c0)       = make_float2(v00, v01);
                *(float2*)(C + (size_t)(r0 + 8) * Dm + c0) = make_float2(v10, v11);
            }
        }
    }
}

// ---------------------------------------------------------------------------
// geo-bias body: one block per (b,n), one thread per m (256 threads).
// ---------------------------------------------------------------------------
__device__ __forceinline__ void geo_body(const float* __restrict__ box,
                                         const int*   __restrict__ mask,
                                         const float* __restrict__ WGw,
                                         const float* __restrict__ WGb,
                                         int b, int n)
{
    __shared__ float Ws[8][32];
    __shared__ float Wc[8][32];
    __shared__ float Wb[8];

    const int t = threadIdx.x;      // m

    for (int idx = t; idx < Hh * 64; idx += 256) {
        int h = idx >> 6, j = idx & 63;
        float w = WGw[idx];
        if (j < 32) Ws[h][j] = w; else Wc[h][j - 32] = w;
    }
    if (t < 8) Wb[t] = WGb[t];
    __syncthreads();

    float4 bn = *(const float4*)(box + (b * Nn + n) * 4);
    float4 bm = *(const float4*)(box + (b * Nn + t) * 4);
    float cx1 = (bn.x + bn.z) * 0.5f, cy1 = (bn.y + bn.w) * 0.5f;
    float w1  = bn.z - bn.x + 1.0f,   h1  = bn.w - bn.y + 1.0f;
    float cx2 = (bm.x + bm.z) * 0.5f, cy2 = (bm.y + bm.w) * 0.5f;
    float w2  = bm.z - bm.x + 1.0f,   h2  = bm.w - bm.y + 1.0f;

    float pos[4];
    pos[0] = logf(fmaxf(fabsf((cx1 - cx2) / w1), 0.001f));
    pos[1] = logf(fmaxf(fabsf((cy1 - cy2) / h1), 0.001f));
    pos[2] = logf(w1 / w2);
    pos[3] = logf(h1 / h2);

    const float dimv[8] = {1.0f, 0.42169650342f, 0.17782794100f, 0.07498942093f,
                           0.03162277660f, 0.01333521432f, 0.00562341325f,
                           0.00237137371f};

    float acc[8];
#pragma unroll
    for (int h = 0; h < 8; ++h) acc[h] = Wb[h];

#pragma unroll
    for (int p = 0; p < 4; ++p) {
        float base = 100.0f * pos[p];
#pragma unroll
        for (int f = 0; f < 8; ++f) {
            float s, c;
            sincosf(base * dimv[f], &s, &c);
            int j = p * 8 + f;
#pragma unroll
            for (int h = 0; h < 8; ++h) {
                acc[h] = fmaf(s, Ws[h][j], acc[h]);
                acc[h] = fmaf(c, Wc[h][j], acc[h]);
            }
        }
    }

    float mterm = (mask[b * Nn + t] == 0) ? -1e9f : 0.0f;
#pragma unroll
    for (int h = 0; h < 8; ++h) {
        float val = logf(fmaxf(acc[h], 1e-6f)) + mterm;
        g_bias[(((b * Hh + h) * Nn) + n) * Nn + t] = val;
    }
}

// ---------------------------------------------------------------------------
// K1: fat kernel.  Blocks [0,1536) = qkv GEMM tiles; [1536, 5632) = geo bias.
// ---------------------------------------------------------------------------
__global__ __launch_bounds__(256)
void fused_qkv_geo(const float* __restrict__ xq, const float* __restrict__ xk,
                   const float* __restrict__ xv,
                   const float* __restrict__ Wq, const float* __restrict__ bq,
                   const float* __restrict__ Wk, const float* __restrict__ bk,
                   const float* __restrict__ Wv, const float* __restrict__ bv,
                   const float* __restrict__ box, const int* __restrict__ msk,
                   const float* __restrict__ WGw, const float* __restrict__ WGb)
{
    const int i = blockIdx.x;
    if (i < 1536) {
        const int bx = i & 7;            // 8 col tiles (N=512)
        const int by = (i >> 3) & 63;    // 64 row tiles (M=4096)
        const int z  = i >> 9;           // 0,1,2 -> q,k,v
        const float* A; const float* W; const float* bias; float* C;
        if (z == 0)      { A = xq; W = Wq; bias = bq; C = g_q; }
        else if (z == 1) { A = xk; W = Wk; bias = bk; C = g_k; }
        else             { A = xv; W = Wv; bias = bv; C = g_v; }
        gemm_tf32_body<true>(A, W, bias, C, by * 64, bx * 64);
    } else {
        const int j = i - 1536;
        geo_body(box, msk, WGw, WGb, j >> 8, j & 255);
    }
}

__global__ __launch_bounds__(256)
void outproj_tf32(const float* __restrict__ Wo, const float* __restrict__ bo,
                  float* __restrict__ out)
{
    gemm_tf32_body<false>(g_attn, Wo, bo, out, blockIdx.y * 64, blockIdx.x * 64);
}

// ---------------------------------------------------------------------------
// K2: fused attention core.  Block = 32 q-rows x 256 keys of one (b,h).
// ---------------------------------------------------------------------------
#define QS(r,c)  sm_f[(r) * 68 + (c)]
#define KS(r,c)  sm_f[2176 + (r) * 68 + (c)]
#define PS(r,c)  sm_f[(r) * 260 + (c)]
#define VS(r,c)  sm_f[8320 + (r) * 68 + (c)]

__global__ __launch_bounds__(256)
void attn_core_kernel()
{
    __shared__ __align__(16) float sm_f[10496];     // 42KB union
    __shared__ float redmax[32][4];
    __shared__ float redsum[32][4];

    const int z = blockIdx.y;                 // b*8+h
    const int b = z >> 3, h = z & 7;
    const int rowBase = blockIdx.x * 32;
    const float* Q  = g_q + (size_t)z * (Nn * DK);
    const float* Kg = g_k + (size_t)z * (Nn * DK);
    const float* Vg = g_v + (size_t)z * (Nn * DK);
    const float* Bias = g_bias + (size_t)z * (Nn * Nn);

    const int t    = threadIdx.x;
    const int lane = t & 31;
    const int w    = t >> 5;
    const int g    = lane >> 2;
    const int tig  = lane & 3;
    const int wr   = w >> 2;
    const int wc   = w & 3;
    const int rl   = wr * 16 + g;

    {
        const int qr = t >> 3, qc = (t & 7) * 8;
        *(float4*)&QS(qr, qc)     = tf32_4(*(const float4*)(Q + (size_t)(rowBase + qr) * DK + qc));
        *(float4*)&QS(qr, qc + 4) = tf32_4(*(const float4*)(Q + (size_t)(rowBase + qr) * DK + qc + 4));
    }

    float s[4][2][4];
#pragma unroll
    for (int cc = 0; cc < 4; ++cc)
#pragma unroll
        for (int nt = 0; nt < 2; ++nt)
#pragma unroll
            for (int i = 0; i < 4; ++i) s[cc][nt][i] = 0.0f;

    const int kr = t >> 2, kc = (t & 3) * 16;
    for (int cc = 0; cc < 4; ++cc) {
        __syncthreads();
#pragma unroll
        for (int i = 0; i < 4; ++i)
            *(float4*)&KS(kr, kc + i * 4) =
                tf32_4(*(const float4*)(Kg + (size_t)(cc * 64 + kr) * DK + kc + i * 4));
        __syncthreads();

#pragma unroll
        for (int ks = 0; ks < 64; ks += 8) {
            uint32_t a0 = __float_as_uint(QS(rl    , ks + tig    ));
            uint32_t a1 = __float_as_uint(QS(rl + 8, ks + tig    ));
            uint32_t a2 = __float_as_uint(QS(rl    , ks + tig + 4));
            uint32_t a3 = __float_as_uint(QS(rl + 8, ks + tig + 4));
#pragma unroll
            for (int nt = 0; nt < 2; ++nt) {
                int nc = wc * 16 + nt * 8 + g;
                uint32_t b0 = __float_as_uint(KS(nc, ks + tig    ));
                uint32_t b1 = __float_as_uint(KS(nc, ks + tig + 4));
                mma_tf32(s[cc][nt], a0, a1, a2, a3, b0, b1);
            }
        }
    }

#pragma unroll
    for (int cc = 0; cc < 4; ++cc)
#pragma unroll
        for (int nt = 0; nt < 2; ++nt) {
            int col = cc * 64 + wc * 16 + nt * 8 + 2 * tig;
            float2 b0v = *(const float2*)(Bias + (size_t)(rowBase + rl) * Nn + col);
            float2 b1v = *(const float2*)(Bias + (size_t)(rowBase + rl + 8) * Nn + col);
            s[cc][nt][0] = fmaf(s[cc][nt][0], 0.125f, b0v.x);
            s[cc][nt][1] = fmaf(s[cc][nt][1], 0.125f, b0v.y);
            s[cc][nt][2] = fmaf(s[cc][nt][2], 0.125f, b1v.x);
            s[cc][nt][3] = fmaf(s[cc][nt][3], 0.125f, b1v.y);
        }

    float m0 = -1e30f, m1 = -1e30f;
#pragma unroll
    for (int cc = 0; cc < 4; ++cc)
#pragma unroll
        for (int nt = 0; nt < 2; ++nt) {
            m0 = fmaxf(m0, fmaxf(s[cc][nt][0], s[cc][nt][1]));
            m1 = fmaxf(m1, fmaxf(s[cc][nt][2], s[cc][nt][3]));
        }
    m0 = fmaxf(m0, __shfl_xor_sync(0xffffffffu, m0, 1));
    m0 = fmaxf(m0, __shfl_xor_sync(0xffffffffu, m0, 2));
    m1 = fmaxf(m1, __shfl_xor_sync(0xffffffffu, m1, 1));
    m1 = fmaxf(m1, __shfl_xor_sync(0xffffffffu, m1, 2));
    if (tig == 0) { redmax[rl][wc] = m0; redmax[rl + 8][wc] = m1; }
    __syncthreads();
    m0 = fmaxf(fmaxf(redmax[rl][0], redmax[rl][1]),
               fmaxf(redmax[rl][2], redmax[rl][3]));
    m1 = fmaxf(fmaxf(redmax[rl + 8][0], redmax[rl + 8][1]),
               fmaxf(redmax[rl + 8][2], redmax[rl + 8][3]));

    float l0 = 0.0f, l1 = 0.0f;
#pragma unroll
    for (int cc = 0; cc < 4; ++cc)
#pragma unroll
        for (int nt = 0; nt < 2; ++nt) {
            s[cc][nt][0] = __expf(s[cc][nt][0] - m0);
            s[cc][nt][1] = __expf(s[cc][nt][1] - m0);
            s[cc][nt][2] = __expf(s[cc][nt][2] - m1);
            s[cc][nt][3] = __expf(s[cc][nt][3] - m1);
            l0 += s[cc][nt][0] + s[cc][nt][1];
            l1 += s[cc][nt][2] + s[cc][nt][3];
        }
    l0 += __shfl_xor_sync(0xffffffffu, l0, 1);
    l0 += __shfl_xor_sync(0xffffffffu, l0, 2);
    l1 += __shfl_xor_sync(0xffffffffu, l1, 1);
    l1 += __shfl_xor_sync(0xffffffffu, l1, 2);
    if (tig == 0) { redsum[rl][wc] = l0; redsum[rl + 8][wc] = l1; }
    __syncthreads();
    l0 = redsum[rl][0] + redsum[rl][1] + redsum[rl][2] + redsum[rl][3];
    l1 = redsum[rl + 8][0] + redsum[rl + 8][1] + redsum[rl + 8][2] + redsum[rl + 8][3];
    const float inv0 = __frcp_rn(l0);
    const float inv1 = __frcp_rn(l1);

    __syncthreads();
#pragma unroll
    for (int cc = 0; cc < 4; ++cc)
#pragma unroll
        for (int nt = 0; nt < 2; ++nt) {
            int col = cc * 64 + wc * 16 + nt * 8 + 2 * tig;
            PS(rl,     col)     = to_tf32(s[cc][nt][0] * inv0);
            PS(rl,     col + 1) = to_tf32(s[cc][nt][1] * inv0);
            PS(rl + 8, col)     = to_tf32(s[cc][nt][2] * inv1);
            PS(rl + 8, col + 1) = to_tf32(s[cc][nt][3] * inv1);
        }

    const int wn = w & 3;
    float o[2][4];
#pragma unroll
    for (int nt = 0; nt < 2; ++nt)
#pragma unroll
        for (int i = 0; i < 4; ++i) o[nt][i] = 0.0f;

    const int vr = t >> 3, vc = (t & 7) * 8;
    for (int kc2 = 0; kc2 < 8; ++kc2) {
        __syncthreads();
        *(float4*)&VS(vr, vc)     = tf32_4(*(const float4*)(Vg + (size_t)(kc2 * 32 + vr) * DK + vc));
        *(float4*)&VS(vr, vc + 4) = tf32_4(*(const float4*)(Vg + (size_t)(kc2 * 32 + vr) * DK + vc + 4));
        __syncthreads();

#pragma unroll
        for (int ks = 0; ks < 32; ks += 8) {
            uint32_t a0 = __float_as_uint(PS(rl    , kc2 * 32 + ks + tig    ));
            uint32_t a1 = __float_as_uint(PS(rl + 8, kc2 * 32 + ks + tig    ));
            uint32_t a2 = __float_as_uint(PS(rl    , kc2 * 32 + ks + tig + 4));
            uint32_t a3 = __float_as_uint(PS(rl + 8, kc2 * 32 + ks + tig + 4));
#pragma unroll
            for (int nt = 0; nt < 2; ++nt) {
                int nc = wn * 16 + nt * 8 + g;
                uint32_t b0 = __float_as_uint(VS(ks + tig    , nc));
                uint32_t b1 = __float_as_uint(VS(ks + tig + 4, nc));
                mma_tf32(o[nt], a0, a1, a2, a3, b0, b1);
            }
        }
    }

#pragma unroll
    for (int nt = 0; nt < 2; ++nt) {
        int d = wn * 16 + nt * 8 + 2 * tig;
        float* p0 = g_attn + ((size_t)(b * Nn + rowBase + rl) * Dm + h * DK + d);
        float* p1 = g_attn + ((size_t)(b * Nn + rowBase + rl + 8) * Dm + h * DK + d);
        *(float2*)p0 = make_float2(o[nt][0], o[nt][1]);
        *(float2*)p1 = make_float2(o[nt][2], o[nt][3]);
    }
}

// ---------------------------------------------------------------------------
extern "C" void kernel_launch(void* const* d_in, const int* in_sizes, int n_in,
                              void* d_out, int out_size)
{
    const float* xq  = (const float*)d_in[0];
    const float* xk  = (const float*)d_in[1];
    const float* xv  = (const float*)d_in[2];
    const float* box = (const float*)d_in[3];
    const int*   msk = (const int*)  d_in[4];
    const float* Wq  = (const float*)d_in[5];
    const float* bq  = (const float*)d_in[6];
    const float* Wk  = (const float*)d_in[7];
    const float* bk  = (const float*)d_in[8];
    const float* Wv  = (const float*)d_in[9];
    const float* bv  = (const float*)d_in[10];
    const float* Wo  = (const float*)d_in[11];
    const float* bo  = (const float*)d_in[12];
    const float* WGw = (const float*)d_in[13];
    const float* WGb = (const float*)d_in[14];
    float* out = (float*)d_out;

    fused_qkv_geo<<<1536 + Bz * Nn, 256>>>(xq, xk, xv, Wq, bq, Wk, bk, Wv, bv,
                                           box, msk, WGw, WGb);
    attn_core_kernel<<<dim3(8, Bz * Hh), 256>>>();
    outproj_tf32<<<dim3(8, 64), 256>>>(Wo, bo, out);
}

// round 12
// speedup vs baseline: 1.1013x; 1.1013x over previous
#include <cuda_runtime.h>
#include <cuda_bf16.h>
#include <cstdint>

// ---------------------------------------------------------------------------
// BoxMultiHeadedAttention  (B=16, N=256, D=512, H=8, d_k=64, dim_g=64)
//
//  K1 fused_qkv_geo : blocks 0..767  -> q,k,v GEMM (tf32 mma, 128x64 tile,
//                     warp tile 32x32, single-buffer + register prefetch)
//                     blocks 768..   -> geo bias (concurrent)
//  K2 attn_core     : O = softmax(bias + qk^T/8) @ V  (fused, tf32 mma)
//  K3 outproj       : out = attn @ Wo + bo
// ---------------------------------------------------------------------------

#define Bz   16
#define Nn   256
#define Dm   512
#define Hh   8
#define DK   64

__device__ float g_q   [Bz*Hh*Nn*DK];
__device__ float g_k   [Bz*Hh*Nn*DK];
__device__ float g_v   [Bz*Hh*Nn*DK];
__device__ float g_bias[Bz*Hh*Nn*Nn];     // geo bias (read-only after K1)
__device__ float g_attn[Bz*Nn*Dm];

__device__ __forceinline__ float to_tf32(float x) {
    uint32_t u;
    asm("cvt.rna.tf32.f32 %0, %1;" : "=r"(u) : "f"(x));
    return __uint_as_float(u);
}

__device__ __forceinline__ void mma_tf32(float c[4],
                                         uint32_t a0, uint32_t a1, uint32_t a2, uint32_t a3,
                                         uint32_t b0, uint32_t b1) {
    asm volatile(
        "mma.sync.aligned.m16n8k8.row.col.f32.tf32.tf32.f32 "
        "{%0,%1,%2,%3}, {%4,%5,%6,%7}, {%8,%9}, {%0,%1,%2,%3};\n"
        : "+f"(c[0]), "+f"(c[1]), "+f"(c[2]), "+f"(c[3])
        : "r"(a0), "r"(a1), "r"(a2), "r"(a3), "r"(b0), "r"(b1));
}

__device__ __forceinline__ float4 tf32_4(float4 v) {
    v.x = to_tf32(v.x); v.y = to_tf32(v.y);
    v.z = to_tf32(v.z); v.w = to_tf32(v.w);
    return v;
}

// ---------------------------------------------------------------------------
// tf32 GEMM body: C[128x64 tile] = A[.,512] @ W[512,512] + bias
// 256 threads / 8 warps; warp tile 32x32 (wm=w>>1 row group, wn=w&1 col
// group).  k-chunk 32, single smem buffer + register prefetch of the next
// chunk between syncs (hidden under the 32-MMA compute block).
// Smem reads per thread per chunk: A 32 fl + B 32 fl for 32 MMAs
// (2.0 fl/MMA vs 3.0 in the 64x64 tile).
// ---------------------------------------------------------------------------
template <bool PERM>
__device__ __forceinline__ void gemm_tf32_body(const float* __restrict__ A,
                                               const float* __restrict__ W,
                                               const float* __restrict__ bias,
                                               float* __restrict__ C,
                                               int rowBase, int colBase)
{
    __shared__ float As[128][36];     // 18.4 KB
    __shared__ float Bs[32][72];      //  9.2 KB

    const int t    = threadIdx.x;
    const int lane = t & 31;
    const int w    = t >> 5;
    const int g    = lane >> 2;
    const int tig  = lane & 3;
    const int wm   = w >> 1;          // 0..3 : 32-row group
    const int wn   = w & 1;           // 0..1 : 32-col group

    const int ar = t >> 1,  ak = (t & 1) * 16;   // A: 128 rows x 32 k, 16/thread
    const int bk = t >> 3,  bn = (t & 7) * 8;    // B: 32 k x 64 n, 8/thread
    const float* Ap = A + (size_t)(rowBase + ar) * Dm + ak;
    const float* Wp = W + (size_t)bk * Dm + colBase + bn;

    float acc[2][4][4];
#pragma unroll
    for (int mt = 0; mt < 2; ++mt)
#pragma unroll
        for (int nt = 0; nt < 4; ++nt)
#pragma unroll
            for (int i = 0; i < 4; ++i) acc[mt][nt][i] = 0.0f;

    // prefetch chunk 0 into registers
    float4 pa[4], pb[2];
#pragma unroll
    for (int i = 0; i < 4; ++i) pa[i] = *(const float4*)(Ap + i * 4);
    pb[0] = *(const float4*)(Wp);
    pb[1] = *(const float4*)(Wp + 4);

    const int NK = Dm / 32;          // 16
    for (int it = 0; it < NK; ++it) {
        // store staged chunk to smem (tf32-rounded)
#pragma unroll
        for (int i = 0; i < 4; ++i)
            *(float4*)&As[ar][ak + i * 4] = tf32_4(pa[i]);
        *(float4*)&Bs[bk][bn]     = tf32_4(pb[0]);
        *(float4*)&Bs[bk][bn + 4] = tf32_4(pb[1]);
        __syncthreads();

        // issue gmem loads for next chunk (overlapped with compute below)
        const bool more = (it + 1 < NK);
        if (more) {
            const int k0 = (it + 1) * 32;
#pragma unroll
            for (int i = 0; i < 4; ++i) pa[i] = *(const float4*)(Ap + k0 + i * 4);
            pb[0] = *(const float4*)(Wp + (size_t)k0 * Dm);
            pb[1] = *(const float4*)(Wp + (size_t)k0 * Dm + 4);
        }

        // compute: 4 ks-steps x 8 MMAs
#pragma unroll
        for (int ks = 0; ks < 32; ks += 8) {
            uint32_t afr[2][4];
#pragma unroll
            for (int mt = 0; mt < 2; ++mt) {
                int mr = wm * 32 + mt * 16 + g;
                afr[mt][0] = __float_as_uint(As[mr    ][ks + tig    ]);
                afr[mt][1] = __float_as_uint(As[mr + 8][ks + tig    ]);
                afr[mt][2] = __float_as_uint(As[mr    ][ks + tig + 4]);
                afr[mt][3] = __float_as_uint(As[mr + 8][ks + tig + 4]);
            }
            uint32_t bfr[4][2];
#pragma unroll
            for (int nt = 0; nt < 4; ++nt) {
                int nc = wn * 32 + nt * 8 + g;
                bfr[nt][0] = __float_as_uint(Bs[ks + tig    ][nc]);
                bfr[nt][1] = __float_as_uint(Bs[ks + tig + 4][nc]);
            }
#pragma unroll
            for (int mt = 0; mt < 2; ++mt)
#pragma unroll
                for (int nt = 0; nt < 4; ++nt)
                    mma_tf32(acc[mt][nt],
                             afr[mt][0], afr[mt][1], afr[mt][2], afr[mt][3],
                             bfr[nt][0], bfr[nt][1]);
        }
        __syncthreads();
    }

#pragma unroll
    for (int mt = 0; mt < 2; ++mt) {
#pragma unroll
        for (int nt = 0; nt < 4; ++nt) {
            int r0 = rowBase + wm * 32 + mt * 16 + g;
            int c0 = colBase + wn * 32 + nt * 8 + 2 * tig;
            float v00 = acc[mt][nt][0] + bias[c0];
            float v01 = acc[mt][nt][1] + bias[c0 + 1];
            float v10 = acc[mt][nt][2] + bias[c0];
            float v11 = acc[mt][nt][3] + bias[c0 + 1];
            if (PERM) {
                int b_ = r0 >> 8, n_ = r0 & 255, h_ = c0 >> 6, d_ = c0 & 63;
                float* p0 = C + ((((b_ * Hh + h_) * Nn) + n_) * DK + d_);
                p0[0] = v00; p0[1] = v01;
                int r1 = r0 + 8;
                int b1_ = r1 >> 8, n1_ = r1 & 255;
                float* p1 = C + ((((b1_ * Hh + h_) * Nn) + n1_) * DK + d_);
                p1[0] = v10; p1[1] = v11;
            } else {
                *(float2*)(C + (size_t)r0 * Dm + c0)       = make_float2(v00, v01);
                *(float2*)(C + (size_t)(r0 + 8) * Dm + c0) = make_float2(v10, v11);
            }
        }
    }
}

// ---------------------------------------------------------------------------
// geo-bias body: one block per (b,n), one thread per m (256 threads).
// ---------------------------------------------------------------------------
__device__ __forceinline__ void geo_body(const float* __restrict__ box,
                                         const int*   __restrict__ mask,
                                         const float* __restrict__ WGw,
                                         const float* __restrict__ WGb,
                                         int b, int n)
{
    __shared__ float Ws[8][32];
    __shared__ float Wc[8][32];
    __shared__ float Wb[8];

    const int t = threadIdx.x;      // m

    for (int idx = t; idx < Hh * 64; idx += 256) {
        int h = idx >> 6, j = idx & 63;
        float w = WGw[idx];
        if (j < 32) Ws[h][j] = w; else Wc[h][j - 32] = w;
    }
    if (t < 8) Wb[t] = WGb[t];
    __syncthreads();

    float4 bn = *(const float4*)(box + (b * Nn + n) * 4);
    float4 bm = *(const float4*)(box + (b * Nn + t) * 4);
    float cx1 = (bn.x + bn.z) * 0.5f, cy1 = (bn.y + bn.w) * 0.5f;
    float w1  = bn.z - bn.x + 1.0f,   h1  = bn.w - bn.y + 1.0f;
    float cx2 = (bm.x + bm.z) * 0.5f, cy2 = (bm.y + bm.w) * 0.5f;
    float w2  = bm.z - bm.x + 1.0f,   h2  = bm.w - bm.y + 1.0f;

    float pos[4];
    pos[0] = logf(fmaxf(fabsf((cx1 - cx2) / w1), 0.001f));
    pos[1] = logf(fmaxf(fabsf((cy1 - cy2) / h1), 0.001f));
    pos[2] = logf(w1 / w2);
    pos[3] = logf(h1 / h2);

    const float dimv[8] = {1.0f, 0.42169650342f, 0.17782794100f, 0.07498942093f,
                           0.03162277660f, 0.01333521432f, 0.00562341325f,
                           0.00237137371f};

    float acc[8];
#pragma unroll
    for (int h = 0; h < 8; ++h) acc[h] = Wb[h];

#pragma unroll
    for (int p = 0; p < 4; ++p) {
        float base = 100.0f * pos[p];
#pragma unroll
        for (int f = 0; f < 8; ++f) {
            float s, c;
            sincosf(base * dimv[f], &s, &c);
            int j = p * 8 + f;
#pragma unroll
            for (int h = 0; h < 8; ++h) {
                acc[h] = fmaf(s, Ws[h][j], acc[h]);
                acc[h] = fmaf(c, Wc[h][j], acc[h]);
            }
        }
    }

    float mterm = (mask[b * Nn + t] == 0) ? -1e9f : 0.0f;
#pragma unroll
    for (int h = 0; h < 8; ++h) {
        float val = logf(fmaxf(acc[h], 1e-6f)) + mterm;
        g_bias[(((b * Hh + h) * Nn) + n) * Nn + t] = val;
    }
}

// ---------------------------------------------------------------------------
// K1: fat kernel.  Blocks [0,768) = qkv GEMM tiles; [768, 4864) = geo bias.
// ---------------------------------------------------------------------------
__global__ __launch_bounds__(256)
void fused_qkv_geo(const float* __restrict__ xq, const float* __restrict__ xk,
                   const float* __restrict__ xv,
                   const float* __restrict__ Wq, const float* __restrict__ bq,
                   const float* __restrict__ Wk, const float* __restrict__ bk,
                   const float* __restrict__ Wv, const float* __restrict__ bv,
                   const float* __restrict__ box, const int* __restrict__ msk,
                   const float* __restrict__ WGw, const float* __restrict__ WGb)
{
    const int i = blockIdx.x;
    if (i < 768) {
        const int bx = i & 7;            // 8 col tiles (N=512)
        const int by = (i >> 3) & 31;    // 32 row tiles (M=4096, 128/tile)
        const int z  = i >> 8;           // 0,1,2 -> q,k,v
        const float* A; const float* W; const float* bias; float* C;
        if (z == 0)      { A = xq; W = Wq; bias = bq; C = g_q; }
        else if (z == 1) { A = xk; W = Wk; bias = bk; C = g_k; }
        else             { A = xv; W = Wv; bias = bv; C = g_v; }
        gemm_tf32_body<true>(A, W, bias, C, by * 128, bx * 64);
    } else {
        const int j = i - 768;
        geo_body(box, msk, WGw, WGb, j >> 8, j & 255);
    }
}

__global__ __launch_bounds__(256)
void outproj_tf32(const float* __restrict__ Wo, const float* __restrict__ bo,
                  float* __restrict__ out)
{
    gemm_tf32_body<false>(g_attn, Wo, bo, out, blockIdx.y * 128, blockIdx.x * 64);
}

// ---------------------------------------------------------------------------
// K2: fused attention core.  Block = 32 q-rows x 256 keys of one (b,h).
// ---------------------------------------------------------------------------
#define QS(r,c)  sm_f[(r) * 68 + (c)]
#define KS(r,c)  sm_f[2176 + (r) * 68 + (c)]
#define PS(r,c)  sm_f[(r) * 260 + (c)]
#define VS(r,c)  sm_f[8320 + (r) * 68 + (c)]

__global__ __launch_bounds__(256)
void attn_core_kernel()
{
    __shared__ __align__(16) float sm_f[10496];     // 42KB union
    __shared__ float redmax[32][4];
    __shared__ float redsum[32][4];

    const int z = blockIdx.y;                 // b*8+h
    const int b = z >> 3, h = z & 7;
    const int rowBase = blockIdx.x * 32;
    const float* Q  = g_q + (size_t)z * (Nn * DK);
    const float* Kg = g_k + (size_t)z * (Nn * DK);
    const float* Vg = g_v + (size_t)z * (Nn * DK);
    const float* Bias = g_bias + (size_t)z * (Nn * Nn);

    const int t    = threadIdx.x;
    const int lane = t & 31;
    const int w    = t >> 5;
    const int g    = lane >> 2;
    const int tig  = lane & 3;
    const int wr   = w >> 2;
    const int wc   = w & 3;
    const int rl   = wr * 16 + g;

    {
        const int qr = t >> 3, qc = (t & 7) * 8;
        *(float4*)&QS(qr, qc)     = tf32_4(*(const float4*)(Q + (size_t)(rowBase + qr) * DK + qc));
        *(float4*)&QS(qr, qc + 4) = tf32_4(*(const float4*)(Q + (size_t)(rowBase + qr) * DK + qc + 4));
    }

    float s[4][2][4];
#pragma unroll
    for (int cc = 0; cc < 4; ++cc)
#pragma unroll
        for (int nt = 0; nt < 2; ++nt)
#pragma unroll
            for (int i = 0; i < 4; ++i) s[cc][nt][i] = 0.0f;

    const int kr = t >> 2, kc = (t & 3) * 16;
    for (int cc = 0; cc < 4; ++cc) {
        __syncthreads();
#pragma unroll
        for (int i = 0; i < 4; ++i)
            *(float4*)&KS(kr, kc + i * 4) =
                tf32_4(*(const float4*)(Kg + (size_t)(cc * 64 + kr) * DK + kc + i * 4));
        __syncthreads();

#pragma unroll
        for (int ks = 0; ks < 64; ks += 8) {
            uint32_t a0 = __float_as_uint(QS(rl    , ks + tig    ));
            uint32_t a1 = __float_as_uint(QS(rl + 8, ks + tig    ));
            uint32_t a2 = __float_as_uint(QS(rl    , ks + tig + 4));
            uint32_t a3 = __float_as_uint(QS(rl + 8, ks + tig + 4));
#pragma unroll
            for (int nt = 0; nt < 2; ++nt) {
                int nc = wc * 16 + nt * 8 + g;
                uint32_t b0 = __float_as_uint(KS(nc, ks + tig    ));
                uint32_t b1 = __float_as_uint(KS(nc, ks + tig + 4));
                mma_tf32(s[cc][nt], a0, a1, a2, a3, b0, b1);
            }
        }
    }

#pragma unroll
    for (int cc = 0; cc < 4; ++cc)
#pragma unroll
        for (int nt = 0; nt < 2; ++nt) {
            int col = cc * 64 + wc * 16 + nt * 8 + 2 * tig;
            float2 b0v = *(const float2*)(Bias + (size_t)(rowBase + rl) * Nn + col);
            float2 b1v = *(const float2*)(Bias + (size_t)(rowBase + rl + 8) * Nn + col);
            s[cc][nt][0] = fmaf(s[cc][nt][0], 0.125f, b0v.x);
            s[cc][nt][1] = fmaf(s[cc][nt][1], 0.125f, b0v.y);
            s[cc][nt][2] = fmaf(s[cc][nt][2], 0.125f, b1v.x);
            s[cc][nt][3] = fmaf(s[cc][nt][3], 0.125f, b1v.y);
        }

    float m0 = -1e30f, m1 = -1e30f;
#pragma unroll
    for (int cc = 0; cc < 4; ++cc)
#pragma unroll
        for (int nt = 0; nt < 2; ++nt) {
            m0 = fmaxf(m0, fmaxf(s[cc][nt][0], s[cc][nt][1]));
            m1 = fmaxf(m1, fmaxf(s[cc][nt][2], s[cc][nt][3]));
        }
    m0 = fmaxf(m0, __shfl_xor_sync(0xffffffffu, m0, 1));
    m0 = fmaxf(m0, __shfl_xor_sync(0xffffffffu, m0, 2));
    m1 = fmaxf(m1, __shfl_xor_sync(0xffffffffu, m1, 1));
    m1 = fmaxf(m1, __shfl_xor_sync(0xffffffffu, m1, 2));
    if (tig == 0) { redmax[rl][wc] = m0; redmax[rl + 8][wc] = m1; }
    __syncthreads();
    m0 = fmaxf(fmaxf(redmax[rl][0], redmax[rl][1]),
               fmaxf(redmax[rl][2], redmax[rl][3]));
    m1 = fmaxf(fmaxf(redmax[rl + 8][0], redmax[rl + 8][1]),
               fmaxf(redmax[rl + 8][2], redmax[rl + 8][3]));

    float l0 = 0.0f, l1 = 0.0f;
#pragma unroll
    for (int cc = 0; cc < 4; ++cc)
#pragma unroll
        for (int nt = 0; nt < 2; ++nt) {
            s[cc][nt][0] = __expf(s[cc][nt][0] - m0);
            s[cc][nt][1] = __expf(s[cc][nt][1] - m0);
            s[cc][nt][2] = __expf(s[cc][nt][2] - m1);
            s[cc][nt][3] = __expf(s[cc][nt][3] - m1);
            l0 += s[cc][nt][0] + s[cc][nt][1];
            l1 += s[cc][nt][2] + s[cc][nt][3];
        }
    l0 += __shfl_xor_sync(0xffffffffu, l0, 1);
    l0 += __shfl_xor_sync(0xffffffffu, l0, 2);
    l1 += __shfl_xor_sync(0xffffffffu, l1, 1);
    l1 += __shfl_xor_sync(0xffffffffu, l1, 2);
    if (tig == 0) { redsum[rl][wc] = l0; redsum[rl + 8][wc] = l1; }
    __syncthreads();
    l0 = redsum[rl][0] + redsum[rl][1] + redsum[rl][2] + redsum[rl][3];
    l1 = redsum[rl + 8][0] + redsum[rl + 8][1] + redsum[rl + 8][2] + redsum[rl + 8][3];
    const float inv0 = __frcp_rn(l0);
    const float inv1 = __frcp_rn(l1);

    __syncthreads();
#pragma unroll
    for (int cc = 0; cc < 4; ++cc)
#pragma unroll
        for (int nt = 0; nt < 2; ++nt) {
            int col = cc * 64 + wc * 16 + nt * 8 + 2 * tig;
            PS(rl,     col)     = to_tf32(s[cc][nt][0] * inv0);
            PS(rl,     col + 1) = to_tf32(s[cc][nt][1] * inv0);
            PS(rl + 8, col)     = to_tf32(s[cc][nt][2] * inv1);
            PS(rl + 8, col + 1) = to_tf32(s[cc][nt][3] * inv1);
        }

    const int wn = w & 3;
    float o[2][4];
#pragma unroll
    for (int nt = 0; nt < 2; ++nt)
#pragma unroll
        for (int i = 0; i < 4; ++i) o[nt][i] = 0.0f;

    const int vr = t >> 3, vc = (t & 7) * 8;
    for (int kc2 = 0; kc2 < 8; ++kc2) {
        __syncthreads();
        *(float4*)&VS(vr, vc)     = tf32_4(*(const float4*)(Vg + (size_t)(kc2 * 32 + vr) * DK + vc));
        *(float4*)&VS(vr, vc + 4) = tf32_4(*(const float4*)(Vg + (size_t)(kc2 * 32 + vr) * DK + vc + 4));
        __syncthreads();

#pragma unroll
        for (int ks = 0; ks < 32; ks += 8) {
            uint32_t a0 = __float_as_uint(PS(rl    , kc2 * 32 + ks + tig    ));
            uint32_t a1 = __float_as_uint(PS(rl + 8, kc2 * 32 + ks + tig    ));
            uint32_t a2 = __float_as_uint(PS(rl    , kc2 * 32 + ks + tig + 4));
            uint32_t a3 = __float_as_uint(PS(rl + 8, kc2 * 32 + ks + tig + 4));
#pragma unroll
            for (int nt = 0; nt < 2; ++nt) {
                int nc = wn * 16 + nt * 8 + g;
                uint32_t b0 = __float_as_uint(VS(ks + tig    , nc));
                uint32_t b1 = __float_as_uint(VS(ks + tig + 4, nc));
                mma_tf32(o[nt], a0, a1, a2, a3, b0, b1);
            }
        }
    }

#pragma unroll
    for (int nt = 0; nt < 2; ++nt) {
        int d = wn * 16 + nt * 8 + 2 * tig;
        float* p0 = g_attn + ((size_t)(b * Nn + rowBase + rl) * Dm + h * DK + d);
        float* p1 = g_attn + ((size_t)(b * Nn + rowBase + rl + 8) * Dm + h * DK + d);
        *(float2*)p0 = make_float2(o[nt][0], o[nt][1]);
        *(float2*)p1 = make_float2(o[nt][2], o[nt][3]);
    }
}

// ---------------------------------------------------------------------------
extern "C" void kernel_launch(void* const* d_in, const int* in_sizes, int n_in,
                              void* d_out, int out_size)
{
    const float* xq  = (const float*)d_in[0];
    const float* xk  = (const float*)d_in[1];
    const float* xv  = (const float*)d_in[2];
    const float* box = (const float*)d_in[3];
    const int*   msk = (const int*)  d_in[4];
    const float* Wq  = (const float*)d_in[5];
    const float* bq  = (const float*)d_in[6];
    const float* Wk  = (const float*)d_in[7];
    const float* bk  = (const float*)d_in[8];
    const float* Wv  = (const float*)d_in[9];
    const float* bv  = (const float*)d_in[10];
    const float* Wo  = (const float*)d_in[11];
    const float* bo  = (const float*)d_in[12];
    const float* WGw = (const float*)d_in[13];
    const float* WGb = (const float*)d_in[14];
    float* out = (float*)d_out;

    fused_qkv_geo<<<768 + Bz * Nn, 256>>>(xq, xk, xv, Wq, bq, Wk, bk, Wv, bv,
                                          box, msk, WGw, WGb);
    attn_core_kernel<<<dim3(8, Bz * Hh), 256>>>();
    outproj_tf32<<<dim3(8, 32), 256>>>(Wo, bo, out);
}

// round 13
// speedup vs baseline: 1.1056x; 1.0039x over previous
#include <cuda_runtime.h>
#include <cuda_bf16.h>
#include <cstdint>

// ---------------------------------------------------------------------------
// BoxMultiHeadedAttention  (B=16, N=256, D=512, H=8, d_k=64, dim_g=64)
//
//  K1 fused_qkv_geo : blocks 0..767  -> q,k,v GEMM (tf32 mma, 128x64 tile,
//                     warp tile 32x32, single-buffer + register prefetch)
//                     blocks 768..   -> geo bias (concurrent)
//  K2 attn_core     : O = softmax(bias + qk^T/8) @ V  (fused, tf32 mma)
//  K3 outproj       : out = attn @ Wo + bo
// ---------------------------------------------------------------------------

#define Bz   16
#define Nn   256
#define Dm   512
#define Hh   8
#define DK   64

__device__ float g_q   [Bz*Hh*Nn*DK];
__device__ float g_k   [Bz*Hh*Nn*DK];
__device__ float g_v   [Bz*Hh*Nn*DK];
__device__ float g_bias[Bz*Hh*Nn*Nn];     // geo bias (read-only after K1)
__device__ float g_attn[Bz*Nn*Dm];

__device__ __forceinline__ float to_tf32(float x) {
    uint32_t u;
    asm("cvt.rna.tf32.f32 %0, %1;" : "=r"(u) : "f"(x));
    return __uint_as_float(u);
}

__device__ __forceinline__ void mma_tf32(float c[4],
                                         uint32_t a0, uint32_t a1, uint32_t a2, uint32_t a3,
                                         uint32_t b0, uint32_t b1) {
    asm volatile(
        "mma.sync.aligned.m16n8k8.row.col.f32.tf32.tf32.f32 "
        "{%0,%1,%2,%3}, {%4,%5,%6,%7}, {%8,%9}, {%0,%1,%2,%3};\n"
        : "+f"(c[0]), "+f"(c[1]), "+f"(c[2]), "+f"(c[3])
        : "r"(a0), "r"(a1), "r"(a2), "r"(a3), "r"(b0), "r"(b1));
}

__device__ __forceinline__ float4 tf32_4(float4 v) {
    v.x = to_tf32(v.x); v.y = to_tf32(v.y);
    v.z = to_tf32(v.z); v.w = to_tf32(v.w);
    return v;
}

// ---------------------------------------------------------------------------
// tf32 GEMM body: C[128x64 tile] = A[.,512] @ W[512,512] + bias
// 256 threads / 8 warps; warp tile 32x32 (wm=w>>1 row group, wn=w&1 col
// group).  k-chunk 32, single smem buffer + register prefetch of the next
// chunk between syncs (hidden under the 32-MMA compute block).
// Smem reads per thread per chunk: A 32 fl + B 32 fl for 32 MMAs
// (2.0 fl/MMA vs 3.0 in the 64x64 tile).
// ---------------------------------------------------------------------------
template <bool PERM>
__device__ __forceinline__ void gemm_tf32_body(const float* __restrict__ A,
                                               const float* __restrict__ W,
                                               const float* __restrict__ bias,
                                               float* __restrict__ C,
                                               int rowBase, int colBase)
{
    __shared__ float As[128][36];     // 18.4 KB
    __shared__ float Bs[32][72];      //  9.2 KB

    const int t    = threadIdx.x;
    const int lane = t & 31;
    const int w    = t >> 5;
    const int g    = lane >> 2;
    const int tig  = lane & 3;
    const int wm   = w >> 1;          // 0..3 : 32-row group
    const int wn   = w & 1;           // 0..1 : 32-col group

    const int ar = t >> 1,  ak = (t & 1) * 16;   // A: 128 rows x 32 k, 16/thread
    const int bk = t >> 3,  bn = (t & 7) * 8;    // B: 32 k x 64 n, 8/thread
    const float* Ap = A + (size_t)(rowBase + ar) * Dm + ak;
    const float* Wp = W + (size_t)bk * Dm + colBase + bn;

    float acc[2][4][4];
#pragma unroll
    for (int mt = 0; mt < 2; ++mt)
#pragma unroll
        for (int nt = 0; nt < 4; ++nt)
#pragma unroll
            for (int i = 0; i < 4; ++i) acc[mt][nt][i] = 0.0f;

    // prefetch chunk 0 into registers
    float4 pa[4], pb[2];
#pragma unroll
    for (int i = 0; i < 4; ++i) pa[i] = *(const float4*)(Ap + i * 4);
    pb[0] = *(const float4*)(Wp);
    pb[1] = *(const float4*)(Wp + 4);

    const int NK = Dm / 32;          // 16
    for (int it = 0; it < NK; ++it) {
        // store staged chunk to smem (tf32-rounded)
#pragma unroll
        for (int i = 0; i < 4; ++i)
            *(float4*)&As[ar][ak + i * 4] = tf32_4(pa[i]);
        *(float4*)&Bs[bk][bn]     = tf32_4(pb[0]);
        *(float4*)&Bs[bk][bn + 4] = tf32_4(pb[1]);
        __syncthreads();

        // issue gmem loads for next chunk (overlapped with compute below)
        const bool more = (it + 1 < NK);
        if (more) {
            const int k0 = (it + 1) * 32;
#pragma unroll
            for (int i = 0; i < 4; ++i) pa[i] = *(const float4*)(Ap + k0 + i * 4);
            pb[0] = *(const float4*)(Wp + (size_t)k0 * Dm);
            pb[1] = *(const float4*)(Wp + (size_t)k0 * Dm + 4);
        }

        // compute: 4 ks-steps x 8 MMAs
#pragma unroll
        for (int ks = 0; ks < 32; ks += 8) {
            uint32_t afr[2][4];
#pragma unroll
            for (int mt = 0; mt < 2; ++mt) {
                int mr = wm * 32 + mt * 16 + g;
                afr[mt][0] = __float_as_uint(As[mr    ][ks + tig    ]);
                afr[mt][1] = __float_as_uint(As[mr + 8][ks + tig    ]);
                afr[mt][2] = __float_as_uint(As[mr    ][ks + tig + 4]);
                afr[mt][3] = __float_as_uint(As[mr + 8][ks + tig + 4]);
            }
            uint32_t bfr[4][2];
#pragma unroll
            for (int nt = 0; nt < 4; ++nt) {
                int nc = wn * 32 + nt * 8 + g;
                bfr[nt][0] = __float_as_uint(Bs[ks + tig    ][nc]);
                bfr[nt][1] = __float_as_uint(Bs[ks + tig + 4][nc]);
            }
#pragma unroll
            for (int mt = 0; mt < 2; ++mt)
#pragma unroll
                for (int nt = 0; nt < 4; ++nt)
                    mma_tf32(acc[mt][nt],
                             afr[mt][0], afr[mt][1], afr[mt][2], afr[mt][3],
                             bfr[nt][0], bfr[nt][1]);
        }
        __syncthreads();
    }

#pragma unroll
    for (int mt = 0; mt < 2; ++mt) {
#pragma unroll
        for (int nt = 0; nt < 4; ++nt) {
            int r0 = rowBase + wm * 32 + mt * 16 + g;
            int c0 = colBase + wn * 32 + nt * 8 + 2 * tig;
            float v00 = acc[mt][nt][0] + bias[c0];
            float v01 = acc[mt][nt][1] + bias[c0 + 1];
            float v10 = acc[mt][nt][2] + bias[c0];
            float v11 = acc[mt][nt][3] + bias[c0 + 1];
            if (PERM) {
                int b_ = r0 >> 8, n_ = r0 & 255, h_ = c0 >> 6, d_ = c0 & 63;
                float* p0 = C + ((((b_ * Hh + h_) * Nn) + n_) * DK + d_);
                p0[0] = v00; p0[1] = v01;
                int r1 = r0 + 8;
                int b1_ = r1 >> 8, n1_ = r1 & 255;
                float* p1 = C + ((((b1_ * Hh + h_) * Nn) + n1_) * DK + d_);
                p1[0] = v10; p1[1] = v11;
            } else {
                *(float2*)(C + (size_t)r0 * Dm + c0)       = make_float2(v00, v01);
                *(float2*)(C + (size_t)(r0 + 8) * Dm + c0) = make_float2(v10, v11);
            }
        }
    }
}

// ---------------------------------------------------------------------------
// geo-bias body: one block per (b,n), one thread per m (256 threads).
// ---------------------------------------------------------------------------
__device__ __forceinline__ void geo_body(const float* __restrict__ box,
                                         const int*   __restrict__ mask,
                                         const float* __restrict__ WGw,
                                         const float* __restrict__ WGb,
                                         int b, int n)
{
    __shared__ float Ws[8][32];
    __shared__ float Wc[8][32];
    __shared__ float Wb[8];

    const int t = threadIdx.x;      // m

    for (int idx = t; idx < Hh * 64; idx += 256) {
        int h = idx >> 6, j = idx & 63;
        float w = WGw[idx];
        if (j < 32) Ws[h][j] = w; else Wc[h][j - 32] = w;
    }
    if (t < 8) Wb[t] = WGb[t];
    __syncthreads();

    float4 bn = *(const float4*)(box + (b * Nn + n) * 4);
    float4 bm = *(const float4*)(box + (b * Nn + t) * 4);
    float cx1 = (bn.x + bn.z) * 0.5f, cy1 = (bn.y + bn.w) * 0.5f;
    float w1  = bn.z - bn.x + 1.0f,   h1  = bn.w - bn.y + 1.0f;
    float cx2 = (bm.x + bm.z) * 0.5f, cy2 = (bm.y + bm.w) * 0.5f;
    float w2  = bm.z - bm.x + 1.0f,   h2  = bm.w - bm.y + 1.0f;

    float pos[4];
    pos[0] = logf(fmaxf(fabsf((cx1 - cx2) / w1), 0.001f));
    pos[1] = logf(fmaxf(fabsf((cy1 - cy2) / h1), 0.001f));
    pos[2] = logf(w1 / w2);
    pos[3] = logf(h1 / h2);

    const float dimv[8] = {1.0f, 0.42169650342f, 0.17782794100f, 0.07498942093f,
                           0.03162277660f, 0.01333521432f, 0.00562341325f,
                           0.00237137371f};

    float acc[8];
#pragma unroll
    for (int h = 0; h < 8; ++h) acc[h] = Wb[h];

#pragma unroll
    for (int p = 0; p < 4; ++p) {
        float base = 100.0f * pos[p];
#pragma unroll
        for (int f = 0; f < 8; ++f) {
            float s, c;
            sincosf(base * dimv[f], &s, &c);
            int j = p * 8 + f;
#pragma unroll
            for (int h = 0; h < 8; ++h) {
                acc[h] = fmaf(s, Ws[h][j], acc[h]);
                acc[h] = fmaf(c, Wc[h][j], acc[h]);
            }
        }
    }

    float mterm = (mask[b * Nn + t] == 0) ? -1e9f : 0.0f;
#pragma unroll
    for (int h = 0; h < 8; ++h) {
        float val = logf(fmaxf(acc[h], 1e-6f)) + mterm;
        g_bias[(((b * Hh + h) * Nn) + n) * Nn + t] = val;
    }
}

// ---------------------------------------------------------------------------
// K1: fat kernel.  Blocks [0,768) = qkv GEMM tiles; [768, 4864) = geo bias.
// ---------------------------------------------------------------------------
__global__ __launch_bounds__(256)
void fused_qkv_geo(const float* __restrict__ xq, const float* __restrict__ xk,
                   const float* __restrict__ xv,
                   const float* __restrict__ Wq, const float* __restrict__ bq,
                   const float* __restrict__ Wk, const float* __restrict__ bk,
                   const float* __restrict__ Wv, const float* __restrict__ bv,
                   const float* __restrict__ box, const int* __restrict__ msk,
                   const float* __restrict__ WGw, const float* __restrict__ WGb)
{
    const int i = blockIdx.x;
    if (i < 768) {
        const int bx = i & 7;            // 8 col tiles (N=512)
        const int by = (i >> 3) & 31;    // 32 row tiles (M=4096, 128/tile)
        const int z  = i >> 8;           // 0,1,2 -> q,k,v
        const float* A; const float* W; const float* bias; float* C;
        if (z == 0)      { A = xq; W = Wq; bias = bq; C = g_q; }
        else if (z == 1) { A = xk; W = Wk; bias = bk; C = g_k; }
        else             { A = xv; W = Wv; bias = bv; C = g_v; }
        gemm_tf32_body<true>(A, W, bias, C, by * 128, bx * 64);
    } else {
        const int j = i - 768;
        geo_body(box, msk, WGw, WGb, j >> 8, j & 255);
    }
}

__global__ __launch_bounds__(256)
void outproj_tf32(const float* __restrict__ Wo, const float* __restrict__ bo,
                  float* __restrict__ out)
{
    gemm_tf32_body<false>(g_attn, Wo, bo, out, blockIdx.y * 128, blockIdx.x * 64);
}

// ---------------------------------------------------------------------------
// K2: fused attention core.  Block = 32 q-rows x 256 keys of one (b,h).
// ---------------------------------------------------------------------------
#define QS(r,c)  sm_f[(r) * 68 + (c)]
#define KS(r,c)  sm_f[2176 + (r) * 68 + (c)]
#define PS(r,c)  sm_f[(r) * 260 + (c)]
#define VS(r,c)  sm_f[8320 + (r) * 68 + (c)]

__global__ __launch_bounds__(256)
void attn_core_kernel()
{
    __shared__ __align__(16) float sm_f[10496];     // 42KB union
    __shared__ float redmax[32][4];
    __shared__ float redsum[32][4];

    const int z = blockIdx.y;                 // b*8+h
    const int b = z >> 3, h = z & 7;
    const int rowBase = blockIdx.x * 32;
    const float* Q  = g_q + (size_t)z * (Nn * DK);
    const float* Kg = g_k + (size_t)z * (Nn * DK);
    const float* Vg = g_v + (size_t)z * (Nn * DK);
    const float* Bias = g_bias + (size_t)z * (Nn * Nn);

    const int t    = threadIdx.x;
    const int lane = t & 31;
    const int w    = t >> 5;
    const int g    = lane >> 2;
    const int tig  = lane & 3;
    const int wr   = w >> 2;
    const int wc   = w & 3;
    const int rl   = wr * 16 + g;

    {
        const int qr = t >> 3, qc = (t & 7) * 8;
        *(float4*)&QS(qr, qc)     = tf32_4(*(const float4*)(Q + (size_t)(rowBase + qr) * DK + qc));
        *(float4*)&QS(qr, qc + 4) = tf32_4(*(const float4*)(Q + (size_t)(rowBase + qr) * DK + qc + 4));
    }

    float s[4][2][4];
#pragma unroll
    for (int cc = 0; cc < 4; ++cc)
#pragma unroll
        for (int nt = 0; nt < 2; ++nt)
#pragma unroll
            for (int i = 0; i < 4; ++i) s[cc][nt][i] = 0.0f;

    const int kr = t >> 2, kc = (t & 3) * 16;
    for (int cc = 0; cc < 4; ++cc) {
        __syncthreads();
#pragma unroll
        for (int i = 0; i < 4; ++i)
            *(float4*)&KS(kr, kc + i * 4) =
                tf32_4(*(const float4*)(Kg + (size_t)(cc * 64 + kr) * DK + kc + i * 4));
        __syncthreads();

#pragma unroll
        for (int ks = 0; ks < 64; ks += 8) {
            uint32_t a0 = __float_as_uint(QS(rl    , ks + tig    ));
            uint32_t a1 = __float_as_uint(QS(rl + 8, ks + tig    ));
            uint32_t a2 = __float_as_uint(QS(rl    , ks + tig + 4));
            uint32_t a3 = __float_as_uint(QS(rl + 8, ks + tig + 4));
#pragma unroll
            for (int nt = 0; nt < 2; ++nt) {
                int nc = wc * 16 + nt * 8 + g;
                uint32_t b0 = __float_as_uint(KS(nc, ks + tig    ));
                uint32_t b1 = __float_as_uint(KS(nc, ks + tig + 4));
                mma_tf32(s[cc][nt], a0, a1, a2, a3, b0, b1);
            }
        }
    }

#pragma unroll
    for (int cc = 0; cc < 4; ++cc)
#pragma unroll
        for (int nt = 0; nt < 2; ++nt) {
            int col = cc * 64 + wc * 16 + nt * 8 + 2 * tig;
            float2 b0v = *(const float2*)(Bias + (size_t)(rowBase + rl) * Nn + col);
            float2 b1v = *(const float2*)(Bias + (size_t)(rowBase + rl + 8) * Nn + col);
            s[cc][nt][0] = fmaf(s[cc][nt][0], 0.125f, b0v.x);
            s[cc][nt][1] = fmaf(s[cc][nt][1], 0.125f, b0v.y);
            s[cc][nt][2] = fmaf(s[cc][nt][2], 0.125f, b1v.x);
            s[cc][nt][3] = fmaf(s[cc][nt][3], 0.125f, b1v.y);
        }

    float m0 = -1e30f, m1 = -1e30f;
#pragma unroll
    for (int cc = 0; cc < 4; ++cc)
#pragma unroll
        for (int nt = 0; nt < 2; ++nt) {
            m0 = fmaxf(m0, fmaxf(s[cc][nt][0], s[cc][nt][1]));
            m1 = fmaxf(m1, fmaxf(s[cc][nt][2], s[cc][nt][3]));
        }
    m0 = fmaxf(m0, __shfl_xor_sync(0xffffffffu, m0, 1));
    m0 = fmaxf(m0, __shfl_xor_sync(0xffffffffu, m0, 2));
    m1 = fmaxf(m1, __shfl_xor_sync(0xffffffffu, m1, 1));
    m1 = fmaxf(m1, __shfl_xor_sync(0xffffffffu, m1, 2));
    if (tig == 0) { redmax[rl][wc] = m0; redmax[rl + 8][wc] = m1; }
    __syncthreads();
    m0 = fmaxf(fmaxf(redmax[rl][0], redmax[rl][1]),
               fmaxf(redmax[rl][2], redmax[rl][3]));
    m1 = fmaxf(fmaxf(redmax[rl + 8][0], redmax[rl + 8][1]),
               fmaxf(redmax[rl + 8][2], redmax[rl + 8][3]));

    float l0 = 0.0f, l1 = 0.0f;
#pragma unroll
    for (int cc = 0; cc < 4; ++cc)
#pragma unroll
        for (int nt = 0; nt < 2; ++nt) {
            s[cc][nt][0] = __expf(s[cc][nt][0] - m0);
            s[cc][nt][1] = __expf(s[cc][nt][1] - m0);
            s[cc][nt][2] = __expf(s[cc][nt][2] - m1);
            s[cc][nt][3] = __expf(s[cc][nt][3] - m1);
            l0 += s[cc][nt][0] + s[cc][nt][1];
            l1 += s[cc][nt][2] + s[cc][nt][3];
        }
    l0 += __shfl_xor_sync(0xffffffffu, l0, 1);
    l0 += __shfl_xor_sync(0xffffffffu, l0, 2);
    l1 += __shfl_xor_sync(0xffffffffu, l1, 1);
    l1 += __shfl_xor_sync(0xffffffffu, l1, 2);
    if (tig == 0) { redsum[rl][wc] = l0; redsum[rl + 8][wc] = l1; }
    __syncthreads();
    l0 = redsum[rl][0] + redsum[rl][1] + redsum[rl][2] + redsum[rl][3];
    l1 = redsum[rl + 8][0] + redsum[rl + 8][1] + redsum[rl + 8][2] + redsum[rl + 8][3];
    const float inv0 = __frcp_rn(l0);
    const float inv1 = __frcp_rn(l1);

    __syncthreads();
#pragma unroll
    for (int cc = 0; cc < 4; ++cc)
#pragma unroll
        for (int nt = 0; nt < 2; ++nt) {
            int col = cc * 64 + wc * 16 + nt * 8 + 2 * tig;
            PS(rl,     col)     = to_tf32(s[cc][nt][0] * inv0);
            PS(rl,     col + 1) = to_tf32(s[cc][nt][1] * inv0);
            PS(rl + 8, col)     = to_tf32(s[cc][nt][2] * inv1);
            PS(rl + 8, col + 1) = to_tf32(s[cc][nt][3] * inv1);
        }

    const int wn = w & 3;
    float o[2][4];
#pragma unroll
    for (int nt = 0; nt < 2; ++nt)
#pragma unroll
        for (int i = 0; i < 4; ++i) o[nt][i] = 0.0f;

    const int vr = t >> 3, vc = (t & 7) * 8;
    for (int kc2 = 0; kc2 < 8; ++kc2) {
        __syncthreads();
        *(float4*)&VS(vr, vc)     = tf32_4(*(const float4*)(Vg + (size_t)(kc2 * 32 + vr) * DK + vc));
        *(float4*)&VS(vr, vc + 4) = tf32_4(*(const float4*)(Vg + (size_t)(kc2 * 32 + vr) * DK + vc + 4));
        __syncthreads();

#pragma unroll
        for (int ks = 0; ks < 32; ks += 8) {
            uint32_t a0 = __float_as_uint(PS(rl    , kc2 * 32 + ks + tig    ));
            uint32_t a1 = __float_as_uint(PS(rl + 8, kc2 * 32 + ks + tig    ));
            uint32_t a2 = __float_as_uint(PS(rl    , kc2 * 32 + ks + tig + 4));
            uint32_t a3 = __float_as_uint(PS(rl + 8, kc2 * 32 + ks + tig + 4));
#pragma unroll
            for (int nt = 0; nt < 2; ++nt) {
                int nc = wn * 16 + nt * 8 + g;
                uint32_t b0 = __float_as_uint(VS(ks + tig    , nc));
                uint32_t b1 = __float_as_uint(VS(ks + tig + 4, nc));
                mma_tf32(o[nt], a0, a1, a2, a3, b0, b1);
            }
        }
    }

#pragma unroll
    for (int nt = 0; nt < 2; ++nt) {
        int d = wn * 16 + nt * 8 + 2 * tig;
        float* p0 = g_attn + ((size_t)(b * Nn + rowBase + rl) * Dm + h * DK + d);
        float* p1 = g_attn + ((size_t)(b * Nn + rowBase + rl + 8) * Dm + h * DK + d);
        *(float2*)p0 = make_float2(o[nt][0], o[nt][1]);
        *(float2*)p1 = make_float2(o[nt][2], o[nt][3]);
    }
}

// ---------------------------------------------------------------------------
extern "C" void kernel_launch(void* const* d_in, const int* in_sizes, int n_in,
                              void* d_out, int out_size)
{
    const float* xq  = (const float*)d_in[0];
    const float* xk  = (const float*)d_in[1];
    const float* xv  = (const float*)d_in[2];
    const float* box = (const float*)d_in[3];
    const int*   msk = (const int*)  d_in[4];
    const float* Wq  = (const float*)d_in[5];
    const float* bq  = (const float*)d_in[6];
    const float* Wk  = (const float*)d_in[7];
    const float* bk  = (const float*)d_in[8];
    const float* Wv  = (const float*)d_in[9];
    const float* bv  = (const float*)d_in[10];
    const float* Wo  = (const float*)d_in[11];
    const float* bo  = (const float*)d_in[12];
    const float* WGw = (const float*)d_in[13];
    const float* WGb = (const float*)d_in[14];
    float* out = (float*)d_out;

    fused_qkv_geo<<<768 + Bz * Nn, 256>>>(xq, xk, xv, Wq, bq, Wk, bk, Wv, bv,
                                          box, msk, WGw, WGb);
    attn_core_kernel<<<dim3(8, Bz * Hh), 256>>>();
    outproj_tf32<<<dim3(8, 32), 256>>>(Wo, bo, out);
}

// round 17
// speedup vs baseline: 1.3321x; 1.2048x over previous
#include <cuda_runtime.h>
#include <cuda_bf16.h>
#include <cstdint>

// ---------------------------------------------------------------------------
// BoxMultiHeadedAttention  (B=16, N=256, D=512, H=8, d_k=64, dim_g=64)
//  K1 fused_qkv_geo : qkv GEMM (tf32 mma) blocks 0..767 ; geo bias blocks 768..
//                     geo uses Cody-Waite + MUFU __sinf/__cosf (fast path)
//  K2 attn_core     : O = softmax(bias + qk^T/8) @ V  (fused, tf32 mma)
//  K3 outproj       : out = attn @ Wo + bo
// ---------------------------------------------------------------------------

#define Bz   16
#define Nn   256
#define Dm   512
#define Hh   8
#define DK   64

__device__ float g_q   [Bz*Hh*Nn*DK];
__device__ float g_k   [Bz*Hh*Nn*DK];
__device__ float g_v   [Bz*Hh*Nn*DK];
__device__ float g_bias[Bz*Hh*Nn*Nn];
__device__ float g_attn[Bz*Nn*Dm];

__device__ __forceinline__ float to_tf32(float x) {
    uint32_t u;
    asm("cvt.rna.tf32.f32 %0, %1;" : "=r"(u) : "f"(x));
    return __uint_as_float(u);
}

__device__ __forceinline__ void mma_tf32(float c[4],
                                         uint32_t a0, uint32_t a1, uint32_t a2, uint32_t a3,
                                         uint32_t b0, uint32_t b1) {
    asm volatile(
        "mma.sync.aligned.m16n8k8.row.col.f32.tf32.tf32.f32 "
        "{%0,%1,%2,%3}, {%4,%5,%6,%7}, {%8,%9}, {%0,%1,%2,%3};\n"
        : "+f"(c[0]), "+f"(c[1]), "+f"(c[2]), "+f"(c[3])
        : "r"(a0), "r"(a1), "r"(a2), "r"(a3), "r"(b0), "r"(b1));
}

__device__ __forceinline__ float4 tf32_4(float4 v) {
    v.x = to_tf32(v.x); v.y = to_tf32(v.y);
    v.z = to_tf32(v.z); v.w = to_tf32(v.w);
    return v;
}

// fast sincos: Cody-Waite reduction to [-pi,pi], then MUFU sin/cos.
// |x| <= ~700 here, k <= ~112; abs error ~1e-6.
__device__ __forceinline__ void fast_sincos(float x, float* s, float* c) {
    const float INV2PI = 0.15915494309189535f;
    const float C1     = 6.2831855f;          // fp32 nearest to 2pi
    const float C2     = -1.7484555e-7f;      // 2pi - C1
    float k = rintf(x * INV2PI);
    float r = fmaf(-k, C1, x);
    r = fmaf(-k, C2, r);
    *s = __sinf(r);
    *c = __cosf(r);
}

// ---------------------------------------------------------------------------
// tf32 GEMM body: C[128x64 tile] = A[.,512] @ W[512,512] + bias
// 256 threads / 8 warps; warp tile 32x32; k-chunk 32; single smem buffer +
// register prefetch.
// ---------------------------------------------------------------------------
template <bool PERM>
__device__ __forceinline__ void gemm_tf32_body(const float* __restrict__ A,
                                               const float* __restrict__ W,
                                               const float* __restrict__ bias,
                                               float* __restrict__ C,
                                               int rowBase, int colBase)
{
    __shared__ float As[128][36];
    __shared__ float Bs[32][72];

    const int t    = threadIdx.x;
    const int lane = t & 31;
    const int w    = t >> 5;
    const int g    = lane >> 2;
    const int tig  = lane & 3;
    const int wm   = w >> 1;
    const int wn   = w & 1;

    const int ar = t >> 1,  ak = (t & 1) * 16;
    const int bk = t >> 3,  bn = (t & 7) * 8;
    const float* Ap = A + (size_t)(rowBase + ar) * Dm + ak;
    const float* Wp = W + (size_t)bk * Dm + colBase + bn;

    float acc[2][4][4];
#pragma unroll
    for (int mt = 0; mt < 2; ++mt)
#pragma unroll
        for (int nt = 0; nt < 4; ++nt)
#pragma unroll
            for (int i = 0; i < 4; ++i) acc[mt][nt][i] = 0.0f;

    float4 pa[4], pb[2];
#pragma unroll
    for (int i = 0; i < 4; ++i) pa[i] = *(const float4*)(Ap + i * 4);
    pb[0] = *(const float4*)(Wp);
    pb[1] = *(const float4*)(Wp + 4);

    const int NK = Dm / 32;
    for (int it = 0; it < NK; ++it) {
#pragma unroll
        for (int i = 0; i < 4; ++i)
            *(float4*)&As[ar][ak + i * 4] = tf32_4(pa[i]);
        *(float4*)&Bs[bk][bn]     = tf32_4(pb[0]);
        *(float4*)&Bs[bk][bn + 4] = tf32_4(pb[1]);
        __syncthreads();

        const bool more = (it + 1 < NK);
        if (more) {
            const int k0 = (it + 1) * 32;
#pragma unroll
            for (int i = 0; i < 4; ++i) pa[i] = *(const float4*)(Ap + k0 + i * 4);
            pb[0] = *(const float4*)(Wp + (size_t)k0 * Dm);
            pb[1] = *(const float4*)(Wp + (size_t)k0 * Dm + 4);
        }

#pragma unroll
        for (int ks = 0; ks < 32; ks += 8) {
            uint32_t afr[2][4];
#pragma unroll
            for (int mt = 0; mt < 2; ++mt) {
                int mr = wm * 32 + mt * 16 + g;
                afr[mt][0] = __float_as_uint(As[mr    ][ks + tig    ]);
                afr[mt][1] = __float_as_uint(As[mr + 8][ks + tig    ]);
                afr[mt][2] = __float_as_uint(As[mr    ][ks + tig + 4]);
                afr[mt][3] = __float_as_uint(As[mr + 8][ks + tig + 4]);
            }
            uint32_t bfr[4][2];
#pragma unroll
            for (int nt = 0; nt < 4; ++nt) {
                int nc = wn * 32 + nt * 8 + g;
                bfr[nt][0] = __float_as_uint(Bs[ks + tig    ][nc]);
                bfr[nt][1] = __float_as_uint(Bs[ks + tig + 4][nc]);
            }
#pragma unroll
            for (int mt = 0; mt < 2; ++mt)
#pragma unroll
                for (int nt = 0; nt < 4; ++nt)
                    mma_tf32(acc[mt][nt],
                             afr[mt][0], afr[mt][1], afr[mt][2], afr[mt][3],
                             bfr[nt][0], bfr[nt][1]);
        }
        __syncthreads();
    }

#pragma unroll
    for (int mt = 0; mt < 2; ++mt) {
#pragma unroll
        for (int nt = 0; nt < 4; ++nt) {
            int r0 = rowBase + wm * 32 + mt * 16 + g;
            int c0 = colBase + wn * 32 + nt * 8 + 2 * tig;
            float v00 = acc[mt][nt][0] + bias[c0];
            float v01 = acc[mt][nt][1] + bias[c0 + 1];
            float v10 = acc[mt][nt][2] + bias[c0];
            float v11 = acc[mt][nt][3] + bias[c0 + 1];
            if (PERM) {
                int b_ = r0 >> 8, n_ = r0 & 255, h_ = c0 >> 6, d_ = c0 & 63;
                float* p0 = C + ((((b_ * Hh + h_) * Nn) + n_) * DK + d_);
                p0[0] = v00; p0[1] = v01;
                int r1 = r0 + 8;
                int b1_ = r1 >> 8, n1_ = r1 & 255;
                float* p1 = C + ((((b1_ * Hh + h_) * Nn) + n1_) * DK + d_);
                p1[0] = v10; p1[1] = v11;
            } else {
                *(float2*)(C + (size_t)r0 * Dm + c0)       = make_float2(v00, v01);
                *(float2*)(C + (size_t)(r0 + 8) * Dm + c0) = make_float2(v10, v11);
            }
        }
    }
}

// ---------------------------------------------------------------------------
// geo-bias body: one block per (b,n), one thread per m.  FAST sincos/log.
// ---------------------------------------------------------------------------
__device__ __forceinline__ void geo_body(const float* __restrict__ box,
                                         const int*   __restrict__ mask,
                                         const float* __restrict__ WGw,
                                         const float* __restrict__ WGb,
                                         int b, int n)
{
    __shared__ float Ws[8][32];
    __shared__ float Wc[8][32];
    __shared__ float Wb[8];

    const int t = threadIdx.x;      // m

    for (int idx = t; idx < Hh * 64; idx += 256) {
        int h = idx >> 6, j = idx & 63;
        float w = WGw[idx];
        if (j < 32) Ws[h][j] = w; else Wc[h][j - 32] = w;
    }
    if (t < 8) Wb[t] = WGb[t];
    __syncthreads();

    float4 bn = *(const float4*)(box + (b * Nn + n) * 4);
    float4 bm = *(const float4*)(box + (b * Nn + t) * 4);
    float cx1 = (bn.x + bn.z) * 0.5f, cy1 = (bn.y + bn.w) * 0.5f;
    float w1  = bn.z - bn.x + 1.0f,   h1  = bn.w - bn.y + 1.0f;
    float cx2 = (bm.x + bm.z) * 0.5f, cy2 = (bm.y + bm.w) * 0.5f;
    float w2  = bm.z - bm.x + 1.0f,   h2  = bm.w - bm.y + 1.0f;

    float pos[4];
    pos[0] = __logf(fmaxf(fabsf((cx1 - cx2) / w1), 0.001f));
    pos[1] = __logf(fmaxf(fabsf((cy1 - cy2) / h1), 0.001f));
    pos[2] = __logf(w1 / w2);
    pos[3] = __logf(h1 / h2);

    const float dimv[8] = {1.0f, 0.42169650342f, 0.17782794100f, 0.07498942093f,
                           0.03162277660f, 0.01333521432f, 0.00562341325f,
                           0.00237137371f};

    float acc[8];
#pragma unroll
    for (int h = 0; h < 8; ++h) acc[h] = Wb[h];

#pragma unroll
    for (int p = 0; p < 4; ++p) {
        float base = 100.0f * pos[p];
#pragma unroll
        for (int f = 0; f < 8; ++f) {
            float s, c;
            fast_sincos(base * dimv[f], &s, &c);
            int j = p * 8 + f;
#pragma unroll
            for (int h = 0; h < 8; ++h) {
                acc[h] = fmaf(s, Ws[h][j], acc[h]);
                acc[h] = fmaf(c, Wc[h][j], acc[h]);
            }
        }
    }

    float mterm = (mask[b * Nn + t] == 0) ? -1e9f : 0.0f;
#pragma unroll
    for (int h = 0; h < 8; ++h) {
        float val = __logf(fmaxf(acc[h], 1e-6f)) + mterm;
        g_bias[(((b * Hh + h) * Nn) + n) * Nn + t] = val;
    }
}

// ---------------------------------------------------------------------------
// K1: fat kernel.  Blocks [0,768) = qkv GEMM tiles; [768, 4864) = geo bias.
// ---------------------------------------------------------------------------
__global__ __launch_bounds__(256)
void fused_qkv_geo(const float* __restrict__ xq, const float* __restrict__ xk,
                   const float* __restrict__ xv,
                   const float* __restrict__ Wq, const float* __restrict__ bq,
                   const float* __restrict__ Wk, const float* __restrict__ bk,
                   const float* __restrict__ Wv, const float* __restrict__ bv,
                   const float* __restrict__ box, const int* __restrict__ msk,
                   const float* __restrict__ WGw, const float* __restrict__ WGb)
{
    const int i = blockIdx.x;
    if (i < 768) {
        const int bx = i & 7;
        const int by = (i >> 3) & 31;
        const int z  = i >> 8;
        const float* A; const float* W; const float* bias; float* C;
        if (z == 0)      { A = xq; W = Wq; bias = bq; C = g_q; }
        else if (z == 1) { A = xk; W = Wk; bias = bk; C = g_k; }
        else             { A = xv; W = Wv; bias = bv; C = g_v; }
        gemm_tf32_body<true>(A, W, bias, C, by * 128, bx * 64);
    } else {
        const int j = i - 768;
        geo_body(box, msk, WGw, WGb, j >> 8, j & 255);
    }
}

__global__ __launch_bounds__(256)
void outproj_tf32(const float* __restrict__ Wo, const float* __restrict__ bo,
                  float* __restrict__ out)
{
    gemm_tf32_body<false>(g_attn, Wo, bo, out, blockIdx.y * 128, blockIdx.x * 64);
}

// ---------------------------------------------------------------------------
// K2: fused attention core.  Block = 32 q-rows x 256 keys of one (b,h).
// ---------------------------------------------------------------------------
#define QS(r,c)  sm_f[(r) * 68 + (c)]
#define KS(r,c)  sm_f[2176 + (r) * 68 + (c)]
#define PS(r,c)  sm_f[(r) * 260 + (c)]
#define VS(r,c)  sm_f[8320 + (r) * 68 + (c)]

__global__ __launch_bounds__(256)
void attn_core_kernel()
{
    __shared__ __align__(16) float sm_f[10496];
    __shared__ float redmax[32][4];
    __shared__ float redsum[32][4];

    const int z = blockIdx.y;
    const int b = z >> 3, h = z & 7;
    const int rowBase = blockIdx.x * 32;
    const float* Q  = g_q + (size_t)z * (Nn * DK);
    const float* Kg = g_k + (size_t)z * (Nn * DK);
    const float* Vg = g_v + (size_t)z * (Nn * DK);
    const float* Bias = g_bias + (size_t)z * (Nn * Nn);

    const int t    = threadIdx.x;
    const int lane = t & 31;
    const int w    = t >> 5;
    const int g    = lane >> 2;
    const int tig  = lane & 3;
    const int wr   = w >> 2;
    const int wc   = w & 3;
    const int rl   = wr * 16 + g;

    {
        const int qr = t >> 3, qc = (t & 7) * 8;
        *(float4*)&QS(qr, qc)     = tf32_4(*(const float4*)(Q + (size_t)(rowBase + qr) * DK + qc));
        *(float4*)&QS(qr, qc + 4) = tf32_4(*(const float4*)(Q + (size_t)(rowBase + qr) * DK + qc + 4));
    }

    float s[4][2][4];
#pragma unroll
    for (int cc = 0; cc < 4; ++cc)
#pragma unroll
        for (int nt = 0; nt < 2; ++nt)
#pragma unroll
            for (int i = 0; i < 4; ++i) s[cc][nt][i] = 0.0f;

    const int kr = t >> 2, kc = (t & 3) * 16;
    for (int cc = 0; cc < 4; ++cc) {
        __syncthreads();
#pragma unroll
        for (int i = 0; i < 4; ++i)
            *(float4*)&KS(kr, kc + i * 4) =
                tf32_4(*(const float4*)(Kg + (size_t)(cc * 64 + kr) * DK + kc + i * 4));
        __syncthreads();

#pragma unroll
        for (int ks = 0; ks < 64; ks += 8) {
            uint32_t a0 = __float_as_uint(QS(rl    , ks + tig    ));
            uint32_t a1 = __float_as_uint(QS(rl + 8, ks + tig    ));
            uint32_t a2 = __float_as_uint(QS(rl    , ks + tig + 4));
            uint32_t a3 = __float_as_uint(QS(rl + 8, ks + tig + 4));
#pragma unroll
            for (int nt = 0; nt < 2; ++nt) {
                int nc = wc * 16 + nt * 8 + g;
                uint32_t b0 = __float_as_uint(KS(nc, ks + tig    ));
                uint32_t b1 = __float_as_uint(KS(nc, ks + tig + 4));
                mma_tf32(s[cc][nt], a0, a1, a2, a3, b0, b1);
            }
        }
    }

#pragma unroll
    for (int cc = 0; cc < 4; ++cc)
#pragma unroll
        for (int nt = 0; nt < 2; ++nt) {
            int col = cc * 64 + wc * 16 + nt * 8 + 2 * tig;
            float2 b0v = *(const float2*)(Bias + (size_t)(rowBase + rl) * Nn + col);
            float2 b1v = *(const float2*)(Bias + (size_t)(rowBase + rl + 8) * Nn + col);
            s[cc][nt][0] = fmaf(s[cc][nt][0], 0.125f, b0v.x);
            s[cc][nt][1] = fmaf(s[cc][nt][1], 0.125f, b0v.y);
            s[cc][nt][2] = fmaf(s[cc][nt][2], 0.125f, b1v.x);
            s[cc][nt][3] = fmaf(s[cc][nt][3], 0.125f, b1v.y);
        }

    float m0 = -1e30f, m1 = -1e30f;
#pragma unroll
    for (int cc = 0; cc < 4; ++cc)
#pragma unroll
        for (int nt = 0; nt < 2; ++nt) {
            m0 = fmaxf(m0, fmaxf(s[cc][nt][0], s[cc][nt][1]));
            m1 = fmaxf(m1, fmaxf(s[cc][nt][2], s[cc][nt][3]));
        }
    m0 = fmaxf(m0, __shfl_xor_sync(0xffffffffu, m0, 1));
    m0 = fmaxf(m0, __shfl_xor_sync(0xffffffffu, m0, 2));
    m1 = fmaxf(m1, __shfl_xor_sync(0xffffffffu, m1, 1));
    m1 = fmaxf(m1, __shfl_xor_sync(0xffffffffu, m1, 2));
    if (tig == 0) { redmax[rl][wc] = m0; redmax[rl + 8][wc] = m1; }
    __syncthreads();
    m0 = fmaxf(fmaxf(redmax[rl][0], redmax[rl][1]),
               fmaxf(redmax[rl][2], redmax[rl][3]));
    m1 = fmaxf(fmaxf(redmax[rl + 8][0], redmax[rl + 8][1]),
               fmaxf(redmax[rl + 8][2], redmax[rl + 8][3]));

    float l0 = 0.0f, l1 = 0.0f;
#pragma unroll
    for (int cc = 0; cc < 4; ++cc)
#pragma unroll
        for (int nt = 0; nt < 2; ++nt) {
            s[cc][nt][0] = __expf(s[cc][nt][0] - m0);
            s[cc][nt][1] = __expf(s[cc][nt][1] - m0);
            s[cc][nt][2] = __expf(s[cc][nt][2] - m1);
            s[cc][nt][3] = __expf(s[cc][nt][3] - m1);
            l0 += s[cc][nt][0] + s[cc][nt][1];
            l1 += s[cc][nt][2] + s[cc][nt][3];
        }
    l0 += __shfl_xor_sync(0xffffffffu, l0, 1);
    l0 += __shfl_xor_sync(0xffffffffu, l0, 2);
    l1 += __shfl_xor_sync(0xffffffffu, l1, 1);
    l1 += __shfl_xor_sync(0xffffffffu, l1, 2);
    if (tig == 0) { redsum[rl][wc] = l0; redsum[rl + 8][wc] = l1; }
    __syncthreads();
    l0 = redsum[rl][0] + redsum[rl][1] + redsum[rl][2] + redsum[rl][3];
    l1 = redsum[rl + 8][0] + redsum[rl + 8][1] + redsum[rl + 8][2] + redsum[rl + 8][3];
    const float inv0 = __frcp_rn(l0);
    const float inv1 = __frcp_rn(l1);

    __syncthreads();
#pragma unroll
    for (int cc = 0; cc < 4; ++cc)
#pragma unroll
        for (int nt = 0; nt < 2; ++nt) {
            int col = cc * 64 + wc * 16 + nt * 8 + 2 * tig;
            PS(rl,     col)     = to_tf32(s[cc][nt][0] * inv0);
            PS(rl,     col + 1) = to_tf32(s[cc][nt][1] * inv0);
            PS(rl + 8, col)     = to_tf32(s[cc][nt][2] * inv1);
            PS(rl + 8, col + 1) = to_tf32(s[cc][nt][3] * inv1);
        }

    const int wn = w & 3;
    float o[2][4];
#pragma unroll
    for (int nt = 0; nt < 2; ++nt)
#pragma unroll
        for (int i = 0; i < 4; ++i) o[nt][i] = 0.0f;

    const int vr = t >> 3, vc = (t & 7) * 8;
    for (int kc2 = 0; kc2 < 8; ++kc2) {
        __syncthreads();
        *(float4*)&VS(vr, vc)     = tf32_4(*(const float4*)(Vg + (size_t)(kc2 * 32 + vr) * DK + vc));
        *(float4*)&VS(vr, vc + 4) = tf32_4(*(const float4*)(Vg + (size_t)(kc2 * 32 + vr) * DK + vc + 4));
        __syncthreads();

#pragma unroll
        for (int ks = 0; ks < 32; ks += 8) {
            uint32_t a0 = __float_as_uint(PS(rl    , kc2 * 32 + ks + tig    ));
            uint32_t a1 = __float_as_uint(PS(rl + 8, kc2 * 32 + ks + tig    ));
            uint32_t a2 = __float_as_uint(PS(rl    , kc2 * 32 + ks + tig + 4));
            uint32_t a3 = __float_as_uint(PS(rl + 8, kc2 * 32 + ks + tig + 4));
#pragma unroll
            for (int nt = 0; nt < 2; ++nt) {
                int nc = wn * 16 + nt * 8 + g;
                uint32_t b0 = __float_as_uint(VS(ks + tig    , nc));
                uint32_t b1 = __float_as_uint(VS(ks + tig + 4, nc));
                mma_tf32(o[nt], a0, a1, a2, a3, b0, b1);
            }
        }
    }

#pragma unroll
    for (int nt = 0; nt < 2; ++nt) {
        int d = wn * 16 + nt * 8 + 2 * tig;
        float* p0 = g_attn + ((size_t)(b * Nn + rowBase + rl) * Dm + h * DK + d);
        float* p1 = g_attn + ((size_t)(b * Nn + rowBase + rl + 8) * Dm + h * DK + d);
        *(float2*)p0 = make_float2(o[nt][0], o[nt][1]);
        *(float2*)p1 = make_float2(o[nt][2], o[nt][3]);
    }
}

// ---------------------------------------------------------------------------
extern "C" void kernel_launch(void* const* d_in, const int* in_sizes, int n_in,
                              void* d_out, int out_size)
{
    const float* xq  = (const float*)d_in[0];
    const float* xk  = (const float*)d_in[1];
    const float* xv  = (const float*)d_in[2];
    const float* box = (const float*)d_in[3];
    const int*   msk = (const int*)  d_in[4];
    const float* Wq  = (const float*)d_in[5];
    const float* bq  = (const float*)d_in[6];
    const float* Wk  = (const float*)d_in[7];
    const float* bk  = (const float*)d_in[8];
    const float* Wv  = (const float*)d_in[9];
    const float* bv  = (const float*)d_in[10];
    const float* Wo  = (const float*)d_in[11];
    const float* bo  = (const float*)d_in[12];
    const float* WGw = (const float*)d_in[13];
    const float* WGb = (const float*)d_in[14];
    float* out = (float*)d_out;

    fused_qkv_geo<<<768 + Bz * Nn, 256>>>(xq, xk, xv, Wq, bq, Wk, bk, Wv, bv,
                                          box, msk, WGw, WGb);
    attn_core_kernel<<<dim3(8, Bz * Hh), 256>>>();
    outproj_tf32<<<dim3(8, 32), 256>>>(Wo, bo, out);
}